// round 13
// baseline (speedup 1.0000x reference)
#include <cuda_runtime.h>
#include <cuda_fp16.h>
#include <math.h>

#define NN 50000
#define EE 1600000
#define H  64
#define CC 16
#define CAP 128             // neighbor bucket capacity (Poisson(32): overflow ~1e-40)

// ---- device scratch ----
__device__ __half2 g_hh[NN * 32];         // dis-scaled linear output (fp16), 128B/node
__device__ float   g_emb[NN * 3 * H];     // concat of the 3 normalized layer outputs
__device__ int     g_cur[NN];             // bucket fill counters == in-degree (zeroed by k_final)
__device__ float   g_dis[NN];             // rsqrt(deg + 1)
__device__ int     g_bucket[NN * CAP];    // per-node neighbor lists (25.6MB)

// ---------------------------------------------------------------
// 1) place edges directly into per-node buckets; counter doubles as degree.
//    8 edges per thread (2x int4) for atomic MLP.
__global__ void k_place(const int4* __restrict__ rows4, const int4* __restrict__ cols4) {
    int e = blockIdx.x * blockDim.x + threadIdx.x;   // pair index over int4s
    int i0 = e * 2;
    if (i0 >= EE / 4) return;
    int4 r = rows4[i0];
    int4 c = cols4[i0];
    int p;
    p = atomicAdd(&g_cur[r.x], 1); if (p < CAP) g_bucket[r.x * CAP + p] = c.x;
    p = atomicAdd(&g_cur[r.y], 1); if (p < CAP) g_bucket[r.y * CAP + p] = c.y;
    p = atomicAdd(&g_cur[r.z], 1); if (p < CAP) g_bucket[r.z * CAP + p] = c.z;
    p = atomicAdd(&g_cur[r.w], 1); if (p < CAP) g_bucket[r.w * CAP + p] = c.w;
    if (i0 + 1 < EE / 4) {
        int4 r2 = rows4[i0 + 1];
        int4 c2 = cols4[i0 + 1];
        p = atomicAdd(&g_cur[r2.x], 1); if (p < CAP) g_bucket[r2.x * CAP + p] = c2.x;
        p = atomicAdd(&g_cur[r2.y], 1); if (p < CAP) g_bucket[r2.y * CAP + p] = c2.y;
        p = atomicAdd(&g_cur[r2.z], 1); if (p < CAP) g_bucket[r2.z * CAP + p] = c2.z;
        p = atomicAdd(&g_cur[r2.w], 1); if (p < CAP) g_bucket[r2.w * CAP + p] = c2.w;
    }
}

// 2) dis = rsqrt(deg+1); rescale layer-1 hh rows in place (hh *= dis[node]).
__global__ void k_disscale() {
    int gt = blockIdx.x * blockDim.x + threadIdx.x;
    int node = gt >> 3;
    int t = gt & 7;
    if (node >= NN) return;
    float d = rsqrtf((float)(g_cur[node] + 1));
    if (t == 0) g_dis[node] = d;
    __half2 dh = __float2half2_rn(d);
    uint4* row = (uint4*)g_hh + node * 8 + t;
    uint4 r = *row;
    __half2* h = (__half2*)&r;
    h[0] = __hmul2(h[0], dh);
    h[1] = __hmul2(h[1], dh);
    h[2] = __hmul2(h[2], dh);
    h[3] = __hmul2(h[3], dh);
    *row = r;
}

// ---------------------------------------------------------------
// 3) h = in @ W, register-tiled 4 nodes x 8 cols per thread.
//    If src!=0, multiplies the row by g_dis[n] before fp16 convert.
__global__ void k_matmul(const float* __restrict__ x, int src, const float* __restrict__ W) {
    __shared__ float Ws[64 * 64];
    __shared__ float xs[64][65];
    int tid = threadIdx.x;   // 0..127

    const float* in; int stride;
    if (src == 0)      { in = x;          stride = 64;  }
    else if (src == 1) { in = g_emb;      stride = 192; }
    else               { in = g_emb + 64; stride = 192; }

    int n0 = blockIdx.x * 64;
    for (int i = tid; i < 64 * 64; i += 128) Ws[i] = W[i];
    {
        int col = tid & 63;
        int rb  = (tid >> 6) * 32;
#pragma unroll
        for (int r = 0; r < 32; r++) {
            int row = rb + r;
            int n = n0 + row;
            xs[row][col] = (n < NN) ? in[(size_t)n * stride + col] : 0.f;
        }
    }
    __syncthreads();

    int tj = (tid & 7) * 8;   // output col base (8 cols)
    int tn = (tid >> 3) * 4;  // node base (4 nodes)
    float acc[4][8];
#pragma unroll
    for (int i = 0; i < 4; i++)
#pragma unroll
        for (int j = 0; j < 8; j++) acc[i][j] = 0.f;

#pragma unroll 8
    for (int k = 0; k < 64; k++) {
        float4 wa = *(const float4*)&Ws[k * 64 + tj];
        float4 wb = *(const float4*)&Ws[k * 64 + tj + 4];
        float xv[4];
        xv[0] = xs[tn + 0][k];
        xv[1] = xs[tn + 1][k];
        xv[2] = xs[tn + 2][k];
        xv[3] = xs[tn + 3][k];
#pragma unroll
        for (int i = 0; i < 4; i++) {
            acc[i][0] = fmaf(xv[i], wa.x, acc[i][0]);
            acc[i][1] = fmaf(xv[i], wa.y, acc[i][1]);
            acc[i][2] = fmaf(xv[i], wa.z, acc[i][2]);
            acc[i][3] = fmaf(xv[i], wa.w, acc[i][3]);
            acc[i][4] = fmaf(xv[i], wb.x, acc[i][4]);
            acc[i][5] = fmaf(xv[i], wb.y, acc[i][5]);
            acc[i][6] = fmaf(xv[i], wb.z, acc[i][6]);
            acc[i][7] = fmaf(xv[i], wb.w, acc[i][7]);
        }
    }

#pragma unroll
    for (int i = 0; i < 4; i++) {
        int n = n0 + tn + i;
        if (n < NN) {
            float d = (src != 0) ? g_dis[n] : 1.f;
            __half2 h0 = __floats2half2_rn(acc[i][0] * d, acc[i][1] * d);
            __half2 h1 = __floats2half2_rn(acc[i][2] * d, acc[i][3] * d);
            __half2 h2 = __floats2half2_rn(acc[i][4] * d, acc[i][5] * d);
            __half2 h3 = __floats2half2_rn(acc[i][6] * d, acc[i][7] * d);
            uint4 o;
            o.x = *(unsigned int*)&h0;
            o.y = *(unsigned int*)&h1;
            o.z = *(unsigned int*)&h2;
            o.w = *(unsigned int*)&h3;
            ((uint4*)g_hh)[n * 8 + (tj >> 3)] = o;
        }
    }
}

// ---------------------------------------------------------------
// helpers
__device__ __forceinline__ void addcvt8(float acc[8], uint4 r) {
    float2 f;
    f = __half22float2(*(__half2*)&r.x); acc[0] += f.x; acc[1] += f.y;
    f = __half22float2(*(__half2*)&r.y); acc[2] += f.x; acc[3] += f.y;
    f = __half22float2(*(__half2*)&r.z); acc[4] += f.x; acc[5] += f.y;
    f = __half22float2(*(__half2*)&r.w); acc[6] += f.x; acc[7] += f.y;
}
__device__ __forceinline__ uint4 hadd4(uint4 a, uint4 b) {
    uint4 o;
    ((__half2*)&o)[0] = __hadd2(((__half2*)&a)[0], ((__half2*)&b)[0]);
    ((__half2*)&o)[1] = __hadd2(((__half2*)&a)[1], ((__half2*)&b)[1]);
    ((__half2*)&o)[2] = __hadd2(((__half2*)&a)[2], ((__half2*)&b)[2]);
    ((__half2*)&o)[3] = __hadd2(((__half2*)&a)[3], ((__half2*)&b)[3]);
    return o;
}

// 4) fused bucket aggregate (unweighted fp16 tree-sum of pre-scaled rows)
//    + self-loop + bias + relu + L2norm + emb write.
//    4 nodes per warp, 8 lanes per node, uint4 per lane.
//    8-edge unrolled mainloop: 8 independent gathers in flight per warp.
__global__ void k_agg(const float* __restrict__ b, int off) {
    int w    = (blockIdx.x * blockDim.x + threadIdx.x) >> 5;
    int lane = threadIdx.x & 31;
    int g = lane >> 3;      // node group 0..3
    int t = lane & 7;       // lane within group
    int node = w * 4 + g;
    bool valid = node < NN;
    int nc = valid ? node : NN - 1;

    int s   = nc * CAP;
    int cnt = g_cur[nc];
    int len = valid ? (cnt < CAP ? cnt : CAP) : 0;
    float dnode = g_dis[nc];

    const uint4* hhv = (const uint4*)g_hh;   // 8 x uint4 per node row

    float acc[8];
#pragma unroll
    for (int j = 0; j < 8; j++) acc[j] = 0.f;

    int i = 0;
    for (; i + 8 <= len; i += 8) {
        int4 ca = *(const int4*)&g_bucket[s + i];
        int4 cb = *(const int4*)&g_bucket[s + i + 4];
        uint4 r0 = hhv[ca.x * 8 + t];
        uint4 r1 = hhv[ca.y * 8 + t];
        uint4 r2 = hhv[ca.z * 8 + t];
        uint4 r3 = hhv[ca.w * 8 + t];
        uint4 r4 = hhv[cb.x * 8 + t];
        uint4 r5 = hhv[cb.y * 8 + t];
        uint4 r6 = hhv[cb.z * 8 + t];
        uint4 r7 = hhv[cb.w * 8 + t];
        // 3-level fp16 tree, then one fp32 flush
        uint4 s01 = hadd4(r0, r1);
        uint4 s23 = hadd4(r2, r3);
        uint4 s45 = hadd4(r4, r5);
        uint4 s67 = hadd4(r6, r7);
        uint4 sA  = hadd4(s01, s23);
        uint4 sB  = hadd4(s45, s67);
        addcvt8(acc, hadd4(sA, sB));
    }
    if (i + 4 <= len) {
        int4 ca = *(const int4*)&g_bucket[s + i];
        uint4 r0 = hhv[ca.x * 8 + t];
        uint4 r1 = hhv[ca.y * 8 + t];
        uint4 r2 = hhv[ca.z * 8 + t];
        uint4 r3 = hhv[ca.w * 8 + t];
        addcvt8(acc, hadd4(hadd4(r0, r1), hadd4(r2, r3)));
        i += 4;
    }
    for (; i < len; i++) {
        int c = g_bucket[s + i];
        addcvt8(acc, hhv[c * 8 + t]);
    }
    // self loop: + hh_scaled[node]
    addcvt8(acc, hhv[nc * 8 + t]);

    // v = dnode * sum + bias ; relu
    float4 b0 = *(const float4*)(b + t * 8);
    float4 b1 = *(const float4*)(b + t * 8 + 4);
    float v[8];
    v[0] = fmaxf(fmaf(dnode, acc[0], b0.x), 0.f);
    v[1] = fmaxf(fmaf(dnode, acc[1], b0.y), 0.f);
    v[2] = fmaxf(fmaf(dnode, acc[2], b0.z), 0.f);
    v[3] = fmaxf(fmaf(dnode, acc[3], b0.w), 0.f);
    v[4] = fmaxf(fmaf(dnode, acc[4], b1.x), 0.f);
    v[5] = fmaxf(fmaf(dnode, acc[5], b1.y), 0.f);
    v[6] = fmaxf(fmaf(dnode, acc[6], b1.z), 0.f);
    v[7] = fmaxf(fmaf(dnode, acc[7], b1.w), 0.f);

    // L2 norm across the 8-lane group
    float ss = 0.f;
#pragma unroll
    for (int j = 0; j < 8; j++) ss = fmaf(v[j], v[j], ss);
#pragma unroll
    for (int m = 4; m >= 1; m >>= 1)
        ss += __shfl_xor_sync(0xFFFFFFFFu, ss, m);
    float inv = 1.f / fmaxf(sqrtf(ss), 1e-12f);

    if (valid) {
        float* dst = g_emb + (size_t)node * 192 + off + t * 8;
        float4 o0; o0.x = v[0] * inv; o0.y = v[1] * inv; o0.z = v[2] * inv; o0.w = v[3] * inv;
        float4 o1; o1.x = v[4] * inv; o1.y = v[5] * inv; o1.z = v[6] * inv; o1.w = v[7] * inv;
        *(float4*)dst = o0;
        *(float4*)(dst + 4) = o1;
    }
}

// ---------------------------------------------------------------
// 5) out = log_softmax(emb @ Wlin + blin). Register-tiled.
//    Also re-zeroes g_cur for graph-replay idempotence.
__global__ void k_final(const float* __restrict__ Wlin, const float* __restrict__ blin,
                        float* __restrict__ out) {
    __shared__ float Ws[192 * 16];
    __shared__ float es[64][193];
    int tid = threadIdx.x;
    int n0 = blockIdx.x * 64;

    {
        int gt = blockIdx.x * 256 + tid;
        if (gt < NN) g_cur[gt] = 0;
    }

    for (int i = tid; i < 192 * 16; i += 256) Ws[i] = Wlin[i];
    {
        int col = tid & 63;
        int rbase = (tid >> 6) * 16;
#pragma unroll
        for (int r = 0; r < 16; r++) {
            int row = rbase + r;
            int n = n0 + row;
            const float* src = g_emb + (size_t)n * 192;
#pragma unroll
            for (int p = 0; p < 3; p++)
                es[row][p * 64 + col] = (n < NN) ? src[p * 64 + col] : 0.f;
        }
    }
    __syncthreads();

    int c  = tid & 15;
    int nb = (tid >> 4) * 4;
    float bias = blin[c];
    float acc[4] = {bias, bias, bias, bias};

#pragma unroll 8
    for (int k = 0; k < 192; k++) {
        float w = Ws[k * 16 + c];
        acc[0] = fmaf(es[nb + 0][k], w, acc[0]);
        acc[1] = fmaf(es[nb + 1][k], w, acc[1]);
        acc[2] = fmaf(es[nb + 2][k], w, acc[2]);
        acc[3] = fmaf(es[nb + 3][k], w, acc[3]);
    }

#pragma unroll
    for (int i = 0; i < 4; i++) {
        float a = acc[i];
        float m = a;
#pragma unroll
        for (int s = 8; s >= 1; s >>= 1)
            m = fmaxf(m, __shfl_xor_sync(0xFFFFFFFFu, m, s));
        float ex = __expf(a - m);
        float sum = ex;
#pragma unroll
        for (int s = 8; s >= 1; s >>= 1)
            sum += __shfl_xor_sync(0xFFFFFFFFu, sum, s);
        int n = n0 + nb + i;
        if (n < NN) out[n * 16 + c] = a - m - logf(sum);
    }
}

// ---------------------------------------------------------------
extern "C" void kernel_launch(void* const* d_in, const int* in_sizes, int n_in,
                              void* d_out, int out_size) {
    const float* x    = (const float*)d_in[0];
    const int*   ei   = (const int*)  d_in[1];
    const float* W1   = (const float*)d_in[2];
    const float* b1   = (const float*)d_in[3];
    const float* W2   = (const float*)d_in[4];
    const float* b2   = (const float*)d_in[5];
    const float* W3   = (const float*)d_in[6];
    const float* b3   = (const float*)d_in[7];
    const float* Wlin = (const float*)d_in[8];
    const float* blin = (const float*)d_in[9];
    float* out = (float*)d_out;

    const int* rows = ei;        // targets
    const int* cols = ei + EE;   // sources

    static cudaStream_t s2 = nullptr;
    static cudaEvent_t ev_fork = nullptr, ev_join = nullptr;
    if (!s2) {
        cudaStreamCreateWithFlags(&s2, cudaStreamNonBlocking);
        cudaEventCreateWithFlags(&ev_fork, cudaEventDisableTiming);
        cudaEventCreateWithFlags(&ev_join, cudaEventDisableTiming);
    }
    cudaStream_t s0 = 0;

    // ---- fork: bucket build on s2, unscaled matmul1 on s0 — independent ----
    cudaEventRecord(ev_fork, s0);
    cudaStreamWaitEvent(s2, ev_fork, 0);
    k_place<<<(EE / 8 + 255) / 256, 256, 0, s2>>>((const int4*)rows, (const int4*)cols);
    cudaEventRecord(ev_join, s2);

    k_matmul<<<(NN + 63) / 64, 128, 0, s0>>>(x, 0, W1);

    // ---- join: dis + in-place scale of hh1, then 3 GCN layers ----
    cudaStreamWaitEvent(s0, ev_join, 0);
    k_disscale<<<(NN * 8 + 255) / 256, 256, 0, s0>>>();

    int aggBlocks = ((NN + 3) / 4 * 32 + 255) / 256;
    k_agg   <<<aggBlocks, 256, 0, s0>>>(b1, 0);
    k_matmul<<<(NN + 63) / 64, 128, 0, s0>>>(x, 1, W2);
    k_agg   <<<aggBlocks, 256, 0, s0>>>(b2, 64);
    k_matmul<<<(NN + 63) / 64, 128, 0, s0>>>(x, 2, W3);
    k_agg   <<<aggBlocks, 256, 0, s0>>>(b3, 128);

    k_final<<<(NN + 63) / 64, 256, 0, s0>>>(Wlin, blin, out);
}

// round 14
// speedup vs baseline: 1.4246x; 1.4246x over previous
#include <cuda_runtime.h>
#include <cuda_fp16.h>
#include <math.h>

#define NN 50000
#define EE 1600000
#define H  64
#define CC 16
#define CAP 128             // neighbor bucket capacity (Poisson(32): overflow ~1e-40)

// ---- device scratch ----
__device__ __half2 g_hh[NN * 32];         // dis-scaled linear output (fp16), 128B/node
__device__ float   g_emb[NN * 3 * H];     // concat of the 3 normalized layer outputs
__device__ int     g_cur[NN];             // bucket fill counters == in-degree (zeroed by k_final)
__device__ float   g_dis[NN];             // rsqrt(deg + 1)
__device__ int     g_bucket[NN * CAP];    // per-node neighbor lists (25.6MB)

// ---------------------------------------------------------------
// 1) place edges directly into per-node buckets; counter doubles as degree.
//    (4 edges per thread — the R12 version; 8/thread regressed badly)
__global__ void k_place(const int4* __restrict__ rows4, const int4* __restrict__ cols4) {
    int e = blockIdx.x * blockDim.x + threadIdx.x;
    if (e >= EE / 4) return;
    int4 r = rows4[e];
    int4 c = cols4[e];
    int p;
    p = atomicAdd(&g_cur[r.x], 1); if (p < CAP) g_bucket[r.x * CAP + p] = c.x;
    p = atomicAdd(&g_cur[r.y], 1); if (p < CAP) g_bucket[r.y * CAP + p] = c.y;
    p = atomicAdd(&g_cur[r.z], 1); if (p < CAP) g_bucket[r.z * CAP + p] = c.z;
    p = atomicAdd(&g_cur[r.w], 1); if (p < CAP) g_bucket[r.w * CAP + p] = c.w;
}

// 2) dis = rsqrt(deg+1); rescale layer-1 hh rows in place (hh *= dis[node]).
__global__ void k_disscale() {
    int gt = blockIdx.x * blockDim.x + threadIdx.x;
    int node = gt >> 3;
    int t = gt & 7;
    if (node >= NN) return;
    float d = rsqrtf((float)(g_cur[node] + 1));
    if (t == 0) g_dis[node] = d;
    __half2 dh = __float2half2_rn(d);
    uint4* row = (uint4*)g_hh + node * 8 + t;
    uint4 r = *row;
    __half2* h = (__half2*)&r;
    h[0] = __hmul2(h[0], dh);
    h[1] = __hmul2(h[1], dh);
    h[2] = __hmul2(h[2], dh);
    h[3] = __hmul2(h[3], dh);
    *row = r;
}

// ---------------------------------------------------------------
// 3) h = in @ W, register-tiled 4 nodes x 8 cols per thread.
//    If src!=0, multiplies the row by g_dis[n] before fp16 convert.
__global__ void k_matmul(const float* __restrict__ x, int src, const float* __restrict__ W) {
    __shared__ float Ws[64 * 64];
    __shared__ float xs[64][65];
    int tid = threadIdx.x;   // 0..127

    const float* in; int stride;
    if (src == 0)      { in = x;          stride = 64;  }
    else if (src == 1) { in = g_emb;      stride = 192; }
    else               { in = g_emb + 64; stride = 192; }

    int n0 = blockIdx.x * 64;
    for (int i = tid; i < 64 * 64; i += 128) Ws[i] = W[i];
    {
        int col = tid & 63;
        int rb  = (tid >> 6) * 32;
#pragma unroll
        for (int r = 0; r < 32; r++) {
            int row = rb + r;
            int n = n0 + row;
            xs[row][col] = (n < NN) ? in[(size_t)n * stride + col] : 0.f;
        }
    }
    __syncthreads();

    int tj = (tid & 7) * 8;   // output col base (8 cols)
    int tn = (tid >> 3) * 4;  // node base (4 nodes)
    float acc[4][8];
#pragma unroll
    for (int i = 0; i < 4; i++)
#pragma unroll
        for (int j = 0; j < 8; j++) acc[i][j] = 0.f;

#pragma unroll 8
    for (int k = 0; k < 64; k++) {
        float4 wa = *(const float4*)&Ws[k * 64 + tj];
        float4 wb = *(const float4*)&Ws[k * 64 + tj + 4];
        float xv[4];
        xv[0] = xs[tn + 0][k];
        xv[1] = xs[tn + 1][k];
        xv[2] = xs[tn + 2][k];
        xv[3] = xs[tn + 3][k];
#pragma unroll
        for (int i = 0; i < 4; i++) {
            acc[i][0] = fmaf(xv[i], wa.x, acc[i][0]);
            acc[i][1] = fmaf(xv[i], wa.y, acc[i][1]);
            acc[i][2] = fmaf(xv[i], wa.z, acc[i][2]);
            acc[i][3] = fmaf(xv[i], wa.w, acc[i][3]);
            acc[i][4] = fmaf(xv[i], wb.x, acc[i][4]);
            acc[i][5] = fmaf(xv[i], wb.y, acc[i][5]);
            acc[i][6] = fmaf(xv[i], wb.z, acc[i][6]);
            acc[i][7] = fmaf(xv[i], wb.w, acc[i][7]);
        }
    }

#pragma unroll
    for (int i = 0; i < 4; i++) {
        int n = n0 + tn + i;
        if (n < NN) {
            float d = (src != 0) ? g_dis[n] : 1.f;
            __half2 h0 = __floats2half2_rn(acc[i][0] * d, acc[i][1] * d);
            __half2 h1 = __floats2half2_rn(acc[i][2] * d, acc[i][3] * d);
            __half2 h2 = __floats2half2_rn(acc[i][4] * d, acc[i][5] * d);
            __half2 h3 = __floats2half2_rn(acc[i][6] * d, acc[i][7] * d);
            uint4 o;
            o.x = *(unsigned int*)&h0;
            o.y = *(unsigned int*)&h1;
            o.z = *(unsigned int*)&h2;
            o.w = *(unsigned int*)&h3;
            ((uint4*)g_hh)[n * 8 + (tj >> 3)] = o;
        }
    }
}

// ---------------------------------------------------------------
// helpers
__device__ __forceinline__ void addcvt8(float acc[8], uint4 r) {
    float2 f;
    f = __half22float2(*(__half2*)&r.x); acc[0] += f.x; acc[1] += f.y;
    f = __half22float2(*(__half2*)&r.y); acc[2] += f.x; acc[3] += f.y;
    f = __half22float2(*(__half2*)&r.z); acc[4] += f.x; acc[5] += f.y;
    f = __half22float2(*(__half2*)&r.w); acc[6] += f.x; acc[7] += f.y;
}
__device__ __forceinline__ uint4 hadd4(uint4 a, uint4 b) {
    uint4 o;
    ((__half2*)&o)[0] = __hadd2(((__half2*)&a)[0], ((__half2*)&b)[0]);
    ((__half2*)&o)[1] = __hadd2(((__half2*)&a)[1], ((__half2*)&b)[1]);
    ((__half2*)&o)[2] = __hadd2(((__half2*)&a)[2], ((__half2*)&b)[2]);
    ((__half2*)&o)[3] = __hadd2(((__half2*)&a)[3], ((__half2*)&b)[3]);
    return o;
}

// 4) fused bucket aggregate (unweighted fp16 tree-sum of pre-scaled rows)
//    + self-loop + bias + relu + L2norm + emb write.
//    4 nodes per warp, 8 lanes per node, uint4 per lane.
//    4-wide loop with NEXT-INDEX PREFETCH: the bucket int4 for iteration i+1
//    issues before the gathers of iteration i, overlapping the two dependent
//    L2 latencies per iteration.
__global__ void k_agg(const float* __restrict__ b, int off) {
    int w    = (blockIdx.x * blockDim.x + threadIdx.x) >> 5;
    int lane = threadIdx.x & 31;
    int g = lane >> 3;      // node group 0..3
    int t = lane & 7;       // lane within group
    int node = w * 4 + g;
    bool valid = node < NN;
    int nc = valid ? node : NN - 1;

    int s   = nc * CAP;
    int cnt = g_cur[nc];
    int len = valid ? (cnt < CAP ? cnt : CAP) : 0;
    float dnode = g_dis[nc];

    const uint4* hhv = (const uint4*)g_hh;   // 8 x uint4 per node row

    float acc[8];
#pragma unroll
    for (int j = 0; j < 8; j++) acc[j] = 0.f;

    int i = 0;
    int4 ca;
    if (len >= 4) ca = *(const int4*)&g_bucket[s];
    for (; i + 4 <= len; i += 4) {
        // prefetch next iteration's indices before this iteration's gathers
        int4 cn = ca;
        if (i + 8 <= len) cn = *(const int4*)&g_bucket[s + i + 4];
        uint4 r0 = hhv[ca.x * 8 + t];
        uint4 r1 = hhv[ca.y * 8 + t];
        uint4 r2 = hhv[ca.z * 8 + t];
        uint4 r3 = hhv[ca.w * 8 + t];
        addcvt8(acc, hadd4(hadd4(r0, r1), hadd4(r2, r3)));
        ca = cn;
    }
    for (; i < len; i++) {
        int c = g_bucket[s + i];
        addcvt8(acc, hhv[c * 8 + t]);
    }
    // self loop: + hh_scaled[node]
    addcvt8(acc, hhv[nc * 8 + t]);

    // v = dnode * sum + bias ; relu
    float4 b0 = *(const float4*)(b + t * 8);
    float4 b1 = *(const float4*)(b + t * 8 + 4);
    float v[8];
    v[0] = fmaxf(fmaf(dnode, acc[0], b0.x), 0.f);
    v[1] = fmaxf(fmaf(dnode, acc[1], b0.y), 0.f);
    v[2] = fmaxf(fmaf(dnode, acc[2], b0.z), 0.f);
    v[3] = fmaxf(fmaf(dnode, acc[3], b0.w), 0.f);
    v[4] = fmaxf(fmaf(dnode, acc[4], b1.x), 0.f);
    v[5] = fmaxf(fmaf(dnode, acc[5], b1.y), 0.f);
    v[6] = fmaxf(fmaf(dnode, acc[6], b1.z), 0.f);
    v[7] = fmaxf(fmaf(dnode, acc[7], b1.w), 0.f);

    // L2 norm across the 8-lane group (xor 4,2,1 stays in-group)
    float ss = 0.f;
#pragma unroll
    for (int j = 0; j < 8; j++) ss = fmaf(v[j], v[j], ss);
#pragma unroll
    for (int m = 4; m >= 1; m >>= 1)
        ss += __shfl_xor_sync(0xFFFFFFFFu, ss, m);
    float inv = 1.f / fmaxf(sqrtf(ss), 1e-12f);

    if (valid) {
        float* dst = g_emb + (size_t)node * 192 + off + t * 8;
        float4 o0; o0.x = v[0] * inv; o0.y = v[1] * inv; o0.z = v[2] * inv; o0.w = v[3] * inv;
        float4 o1; o1.x = v[4] * inv; o1.y = v[5] * inv; o1.z = v[6] * inv; o1.w = v[7] * inv;
        *(float4*)dst = o0;
        *(float4*)(dst + 4) = o1;
    }
}

// ---------------------------------------------------------------
// 5) out = log_softmax(emb @ Wlin + blin). Register-tiled.
//    Also re-zeroes g_cur for graph-replay idempotence.
__global__ void k_final(const float* __restrict__ Wlin, const float* __restrict__ blin,
                        float* __restrict__ out) {
    __shared__ float Ws[192 * 16];
    __shared__ float es[64][193];
    int tid = threadIdx.x;
    int n0 = blockIdx.x * 64;

    {
        int gt = blockIdx.x * 256 + tid;
        if (gt < NN) g_cur[gt] = 0;
    }

    for (int i = tid; i < 192 * 16; i += 256) Ws[i] = Wlin[i];
    {
        int col = tid & 63;
        int rbase = (tid >> 6) * 16;
#pragma unroll
        for (int r = 0; r < 16; r++) {
            int row = rbase + r;
            int n = n0 + row;
            const float* src = g_emb + (size_t)n * 192;
#pragma unroll
            for (int p = 0; p < 3; p++)
                es[row][p * 64 + col] = (n < NN) ? src[p * 64 + col] : 0.f;
        }
    }
    __syncthreads();

    int c  = tid & 15;
    int nb = (tid >> 4) * 4;
    float bias = blin[c];
    float acc[4] = {bias, bias, bias, bias};

#pragma unroll 8
    for (int k = 0; k < 192; k++) {
        float w = Ws[k * 16 + c];
        acc[0] = fmaf(es[nb + 0][k], w, acc[0]);
        acc[1] = fmaf(es[nb + 1][k], w, acc[1]);
        acc[2] = fmaf(es[nb + 2][k], w, acc[2]);
        acc[3] = fmaf(es[nb + 3][k], w, acc[3]);
    }

#pragma unroll
    for (int i = 0; i < 4; i++) {
        float a = acc[i];
        float m = a;
#pragma unroll
        for (int s = 8; s >= 1; s >>= 1)
            m = fmaxf(m, __shfl_xor_sync(0xFFFFFFFFu, m, s));
        float ex = __expf(a - m);
        float sum = ex;
#pragma unroll
        for (int s = 8; s >= 1; s >>= 1)
            sum += __shfl_xor_sync(0xFFFFFFFFu, sum, s);
        int n = n0 + nb + i;
        if (n < NN) out[n * 16 + c] = a - m - logf(sum);
    }
}

// ---------------------------------------------------------------
extern "C" void kernel_launch(void* const* d_in, const int* in_sizes, int n_in,
                              void* d_out, int out_size) {
    const float* x    = (const float*)d_in[0];
    const int*   ei   = (const int*)  d_in[1];
    const float* W1   = (const float*)d_in[2];
    const float* b1   = (const float*)d_in[3];
    const float* W2   = (const float*)d_in[4];
    const float* b2   = (const float*)d_in[5];
    const float* W3   = (const float*)d_in[6];
    const float* b3   = (const float*)d_in[7];
    const float* Wlin = (const float*)d_in[8];
    const float* blin = (const float*)d_in[9];
    float* out = (float*)d_out;

    const int* rows = ei;        // targets
    const int* cols = ei + EE;   // sources

    static cudaStream_t s2 = nullptr;
    static cudaEvent_t ev_fork = nullptr, ev_join = nullptr;
    if (!s2) {
        cudaStreamCreateWithFlags(&s2, cudaStreamNonBlocking);
        cudaEventCreateWithFlags(&ev_fork, cudaEventDisableTiming);
        cudaEventCreateWithFlags(&ev_join, cudaEventDisableTiming);
    }
    cudaStream_t s0 = 0;

    // ---- fork: bucket build on s2, unscaled matmul1 on s0 — independent ----
    cudaEventRecord(ev_fork, s0);
    cudaStreamWaitEvent(s2, ev_fork, 0);
    k_place<<<(EE / 4 + 255) / 256, 256, 0, s2>>>((const int4*)rows, (const int4*)cols);
    cudaEventRecord(ev_join, s2);

    k_matmul<<<(NN + 63) / 64, 128, 0, s0>>>(x, 0, W1);

    // ---- join: dis + in-place scale of hh1, then 3 GCN layers ----
    cudaStreamWaitEvent(s0, ev_join, 0);
    k_disscale<<<(NN * 8 + 255) / 256, 256, 0, s0>>>();

    int aggBlocks = ((NN + 3) / 4 * 32 + 255) / 256;
    k_agg   <<<aggBlocks, 256, 0, s0>>>(b1, 0);
    k_matmul<<<(NN + 63) / 64, 128, 0, s0>>>(x, 1, W2);
    k_agg   <<<aggBlocks, 256, 0, s0>>>(b2, 64);
    k_matmul<<<(NN + 63) / 64, 128, 0, s0>>>(x, 2, W3);
    k_agg   <<<aggBlocks, 256, 0, s0>>>(b3, 128);

    k_final<<<(NN + 63) / 64, 256, 0, s0>>>(Wlin, blin, out);
}

// round 15
// speedup vs baseline: 1.4436x; 1.0133x over previous
#include <cuda_runtime.h>
#include <cuda_fp16.h>
#include <math.h>

#define NN 50000
#define EE 1600000
#define H  64
#define CC 16
#define CAP 128             // neighbor bucket capacity (Poisson(32): overflow ~1e-40)

// ---- device scratch ----
__device__ __half2 g_hh[NN * 32];         // dis-scaled linear output (fp16), 128B/node
__device__ float   g_emb[NN * 3 * H];     // concat of the 3 normalized layer outputs
__device__ int     g_cur[NN];             // bucket fill counters == in-degree (zeroed by k_final)
__device__ float   g_dis[NN];             // rsqrt(deg + 1)
__device__ int     g_bucket[NN * CAP];    // per-node neighbor lists (25.6MB)

// ---------------------------------------------------------------
// 1) place edges directly into per-node buckets; counter doubles as degree.
//    Scalar 1 edge/thread: max thread-level atomic parallelism.
__global__ void k_place(const int* __restrict__ rows, const int* __restrict__ cols) {
    int e = blockIdx.x * blockDim.x + threadIdx.x;
    if (e >= EE) return;
    int r = rows[e];
    int c = cols[e];
    int p = atomicAdd(&g_cur[r], 1);
    if (p < CAP) g_bucket[r * CAP + p] = c;
}

// 2) dis = rsqrt(deg+1); rescale layer-1 hh rows in place (hh *= dis[node]).
__global__ void k_disscale() {
    int gt = blockIdx.x * blockDim.x + threadIdx.x;
    int node = gt >> 3;
    int t = gt & 7;
    if (node >= NN) return;
    float d = rsqrtf((float)(g_cur[node] + 1));
    if (t == 0) g_dis[node] = d;
    __half2 dh = __float2half2_rn(d);
    uint4* row = (uint4*)g_hh + node * 8 + t;
    uint4 r = *row;
    __half2* h = (__half2*)&r;
    h[0] = __hmul2(h[0], dh);
    h[1] = __hmul2(h[1], dh);
    h[2] = __hmul2(h[2], dh);
    h[3] = __hmul2(h[3], dh);
    *row = r;
}

// ---------------------------------------------------------------
// 3) h = in @ W, register-tiled 4 nodes x 8 cols per thread.
//    If src!=0, multiplies the row by g_dis[n] before fp16 convert.
__global__ void k_matmul(const float* __restrict__ x, int src, const float* __restrict__ W) {
    __shared__ float Ws[64 * 64];
    __shared__ float xs[64][65];
    int tid = threadIdx.x;   // 0..127

    const float* in; int stride;
    if (src == 0)      { in = x;          stride = 64;  }
    else if (src == 1) { in = g_emb;      stride = 192; }
    else               { in = g_emb + 64; stride = 192; }

    int n0 = blockIdx.x * 64;
    for (int i = tid; i < 64 * 64; i += 128) Ws[i] = W[i];
    {
        int col = tid & 63;
        int rb  = (tid >> 6) * 32;
#pragma unroll
        for (int r = 0; r < 32; r++) {
            int row = rb + r;
            int n = n0 + row;
            xs[row][col] = (n < NN) ? in[(size_t)n * stride + col] : 0.f;
        }
    }
    __syncthreads();

    int tj = (tid & 7) * 8;   // output col base (8 cols)
    int tn = (tid >> 3) * 4;  // node base (4 nodes)
    float acc[4][8];
#pragma unroll
    for (int i = 0; i < 4; i++)
#pragma unroll
        for (int j = 0; j < 8; j++) acc[i][j] = 0.f;

#pragma unroll 8
    for (int k = 0; k < 64; k++) {
        float4 wa = *(const float4*)&Ws[k * 64 + tj];
        float4 wb = *(const float4*)&Ws[k * 64 + tj + 4];
        float xv[4];
        xv[0] = xs[tn + 0][k];
        xv[1] = xs[tn + 1][k];
        xv[2] = xs[tn + 2][k];
        xv[3] = xs[tn + 3][k];
#pragma unroll
        for (int i = 0; i < 4; i++) {
            acc[i][0] = fmaf(xv[i], wa.x, acc[i][0]);
            acc[i][1] = fmaf(xv[i], wa.y, acc[i][1]);
            acc[i][2] = fmaf(xv[i], wa.z, acc[i][2]);
            acc[i][3] = fmaf(xv[i], wa.w, acc[i][3]);
            acc[i][4] = fmaf(xv[i], wb.x, acc[i][4]);
            acc[i][5] = fmaf(xv[i], wb.y, acc[i][5]);
            acc[i][6] = fmaf(xv[i], wb.z, acc[i][6]);
            acc[i][7] = fmaf(xv[i], wb.w, acc[i][7]);
        }
    }

#pragma unroll
    for (int i = 0; i < 4; i++) {
        int n = n0 + tn + i;
        if (n < NN) {
            float d = (src != 0) ? g_dis[n] : 1.f;
            __half2 h0 = __floats2half2_rn(acc[i][0] * d, acc[i][1] * d);
            __half2 h1 = __floats2half2_rn(acc[i][2] * d, acc[i][3] * d);
            __half2 h2 = __floats2half2_rn(acc[i][4] * d, acc[i][5] * d);
            __half2 h3 = __floats2half2_rn(acc[i][6] * d, acc[i][7] * d);
            uint4 o;
            o.x = *(unsigned int*)&h0;
            o.y = *(unsigned int*)&h1;
            o.z = *(unsigned int*)&h2;
            o.w = *(unsigned int*)&h3;
            ((uint4*)g_hh)[n * 8 + (tj >> 3)] = o;
        }
    }
}

// ---------------------------------------------------------------
// helpers
__device__ __forceinline__ void addcvt8(float acc[8], uint4 r) {
    float2 f;
    f = __half22float2(*(__half2*)&r.x); acc[0] += f.x; acc[1] += f.y;
    f = __half22float2(*(__half2*)&r.y); acc[2] += f.x; acc[3] += f.y;
    f = __half22float2(*(__half2*)&r.z); acc[4] += f.x; acc[5] += f.y;
    f = __half22float2(*(__half2*)&r.w); acc[6] += f.x; acc[7] += f.y;
}
__device__ __forceinline__ uint4 hadd4(uint4 a, uint4 b) {
    uint4 o;
    ((__half2*)&o)[0] = __hadd2(((__half2*)&a)[0], ((__half2*)&b)[0]);
    ((__half2*)&o)[1] = __hadd2(((__half2*)&a)[1], ((__half2*)&b)[1]);
    ((__half2*)&o)[2] = __hadd2(((__half2*)&a)[2], ((__half2*)&b)[2]);
    ((__half2*)&o)[3] = __hadd2(((__half2*)&a)[3], ((__half2*)&b)[3]);
    return o;
}

// 4) fused bucket aggregate (unweighted fp16 tree-sum of pre-scaled rows)
//    + self-loop + bias + relu + L2norm + emb write.
//    4 nodes per warp, 8 lanes per node, uint4 per lane, next-index prefetch.
//    __launch_bounds__(256, 6): cap regs to lift occupancy to 48 warps/SM.
__global__ void __launch_bounds__(256, 6) k_agg(const float* __restrict__ b, int off) {
    int w    = (blockIdx.x * blockDim.x + threadIdx.x) >> 5;
    int lane = threadIdx.x & 31;
    int g = lane >> 3;      // node group 0..3
    int t = lane & 7;       // lane within group
    int node = w * 4 + g;
    bool valid = node < NN;
    int nc = valid ? node : NN - 1;

    int s   = nc * CAP;
    int cnt = g_cur[nc];
    int len = valid ? (cnt < CAP ? cnt : CAP) : 0;
    float dnode = g_dis[nc];

    const uint4* hhv = (const uint4*)g_hh;   // 8 x uint4 per node row

    float acc[8];
#pragma unroll
    for (int j = 0; j < 8; j++) acc[j] = 0.f;

    int i = 0;
    int4 ca;
    if (len >= 4) ca = *(const int4*)&g_bucket[s];
    for (; i + 4 <= len; i += 4) {
        // prefetch next iteration's indices before this iteration's gathers
        int4 cn = ca;
        if (i + 8 <= len) cn = *(const int4*)&g_bucket[s + i + 4];
        uint4 r0 = hhv[ca.x * 8 + t];
        uint4 r1 = hhv[ca.y * 8 + t];
        uint4 r2 = hhv[ca.z * 8 + t];
        uint4 r3 = hhv[ca.w * 8 + t];
        addcvt8(acc, hadd4(hadd4(r0, r1), hadd4(r2, r3)));
        ca = cn;
    }
    for (; i < len; i++) {
        int c = g_bucket[s + i];
        addcvt8(acc, hhv[c * 8 + t]);
    }
    // self loop: + hh_scaled[node]
    addcvt8(acc, hhv[nc * 8 + t]);

    // v = dnode * sum + bias ; relu
    float4 b0 = *(const float4*)(b + t * 8);
    float4 b1 = *(const float4*)(b + t * 8 + 4);
    float v[8];
    v[0] = fmaxf(fmaf(dnode, acc[0], b0.x), 0.f);
    v[1] = fmaxf(fmaf(dnode, acc[1], b0.y), 0.f);
    v[2] = fmaxf(fmaf(dnode, acc[2], b0.z), 0.f);
    v[3] = fmaxf(fmaf(dnode, acc[3], b0.w), 0.f);
    v[4] = fmaxf(fmaf(dnode, acc[4], b1.x), 0.f);
    v[5] = fmaxf(fmaf(dnode, acc[5], b1.y), 0.f);
    v[6] = fmaxf(fmaf(dnode, acc[6], b1.z), 0.f);
    v[7] = fmaxf(fmaf(dnode, acc[7], b1.w), 0.f);

    // L2 norm across the 8-lane group (xor 4,2,1 stays in-group)
    float ss = 0.f;
#pragma unroll
    for (int j = 0; j < 8; j++) ss = fmaf(v[j], v[j], ss);
#pragma unroll
    for (int m = 4; m >= 1; m >>= 1)
        ss += __shfl_xor_sync(0xFFFFFFFFu, ss, m);
    float inv = 1.f / fmaxf(sqrtf(ss), 1e-12f);

    if (valid) {
        float* dst = g_emb + (size_t)node * 192 + off + t * 8;
        float4 o0; o0.x = v[0] * inv; o0.y = v[1] * inv; o0.z = v[2] * inv; o0.w = v[3] * inv;
        float4 o1; o1.x = v[4] * inv; o1.y = v[5] * inv; o1.z = v[6] * inv; o1.w = v[7] * inv;
        *(float4*)dst = o0;
        *(float4*)(dst + 4) = o1;
    }
}

// ---------------------------------------------------------------
// 5) out = log_softmax(emb @ Wlin + blin). Register-tiled.
//    Also re-zeroes g_cur for graph-replay idempotence.
__global__ void k_final(const float* __restrict__ Wlin, const float* __restrict__ blin,
                        float* __restrict__ out) {
    __shared__ float Ws[192 * 16];
    __shared__ float es[64][193];
    int tid = threadIdx.x;
    int n0 = blockIdx.x * 64;

    {
        int gt = blockIdx.x * 256 + tid;
        if (gt < NN) g_cur[gt] = 0;
    }

    for (int i = tid; i < 192 * 16; i += 256) Ws[i] = Wlin[i];
    {
        int col = tid & 63;
        int rbase = (tid >> 6) * 16;
#pragma unroll
        for (int r = 0; r < 16; r++) {
            int row = rbase + r;
            int n = n0 + row;
            const float* src = g_emb + (size_t)n * 192;
#pragma unroll
            for (int p = 0; p < 3; p++)
                es[row][p * 64 + col] = (n < NN) ? src[p * 64 + col] : 0.f;
        }
    }
    __syncthreads();

    int c  = tid & 15;
    int nb = (tid >> 4) * 4;
    float bias = blin[c];
    float acc[4] = {bias, bias, bias, bias};

#pragma unroll 8
    for (int k = 0; k < 192; k++) {
        float w = Ws[k * 16 + c];
        acc[0] = fmaf(es[nb + 0][k], w, acc[0]);
        acc[1] = fmaf(es[nb + 1][k], w, acc[1]);
        acc[2] = fmaf(es[nb + 2][k], w, acc[2]);
        acc[3] = fmaf(es[nb + 3][k], w, acc[3]);
    }

#pragma unroll
    for (int i = 0; i < 4; i++) {
        float a = acc[i];
        float m = a;
#pragma unroll
        for (int s = 8; s >= 1; s >>= 1)
            m = fmaxf(m, __shfl_xor_sync(0xFFFFFFFFu, m, s));
        float ex = __expf(a - m);
        float sum = ex;
#pragma unroll
        for (int s = 8; s >= 1; s >>= 1)
            sum += __shfl_xor_sync(0xFFFFFFFFu, sum, s);
        int n = n0 + nb + i;
        if (n < NN) out[n * 16 + c] = a - m - logf(sum);
    }
}

// ---------------------------------------------------------------
extern "C" void kernel_launch(void* const* d_in, const int* in_sizes, int n_in,
                              void* d_out, int out_size) {
    const float* x    = (const float*)d_in[0];
    const int*   ei   = (const int*)  d_in[1];
    const float* W1   = (const float*)d_in[2];
    const float* b1   = (const float*)d_in[3];
    const float* W2   = (const float*)d_in[4];
    const float* b2   = (const float*)d_in[5];
    const float* W3   = (const float*)d_in[6];
    const float* b3   = (const float*)d_in[7];
    const float* Wlin = (const float*)d_in[8];
    const float* blin = (const float*)d_in[9];
    float* out = (float*)d_out;

    const int* rows = ei;        // targets
    const int* cols = ei + EE;   // sources

    static cudaStream_t s2 = nullptr;
    static cudaEvent_t ev_fork = nullptr, ev_join = nullptr;
    if (!s2) {
        cudaStreamCreateWithFlags(&s2, cudaStreamNonBlocking);
        cudaEventCreateWithFlags(&ev_fork, cudaEventDisableTiming);
        cudaEventCreateWithFlags(&ev_join, cudaEventDisableTiming);
    }
    cudaStream_t s0 = 0;

    // ---- fork: bucket build on s2, unscaled matmul1 on s0 — independent ----
    cudaEventRecord(ev_fork, s0);
    cudaStreamWaitEvent(s2, ev_fork, 0);
    k_place<<<(EE + 255) / 256, 256, 0, s2>>>(rows, cols);
    cudaEventRecord(ev_join, s2);

    k_matmul<<<(NN + 63) / 64, 128, 0, s0>>>(x, 0, W1);

    // ---- join: dis + in-place scale of hh1, then 3 GCN layers ----
    cudaStreamWaitEvent(s0, ev_join, 0);
    k_disscale<<<(NN * 8 + 255) / 256, 256, 0, s0>>>();

    int aggBlocks = ((NN + 3) / 4 * 32 + 255) / 256;
    k_agg   <<<aggBlocks, 256, 0, s0>>>(b1, 0);
    k_matmul<<<(NN + 63) / 64, 128, 0, s0>>>(x, 1, W2);
    k_agg   <<<aggBlocks, 256, 0, s0>>>(b2, 64);
    k_matmul<<<(NN + 63) / 64, 128, 0, s0>>>(x, 2, W3);
    k_agg   <<<aggBlocks, 256, 0, s0>>>(b3, 128);

    k_final<<<(NN + 63) / 64, 256, 0, s0>>>(Wlin, blin, out);
}